// round 3
// baseline (speedup 1.0000x reference)
#include <cuda_runtime.h>
#include <cstdint>

#define NSYM   12
#define HID    100
#define BATCH  16384
#define GATES  400            // 4*HID
#define LSTM_THREADS 416      // 13 warps; threads 0..399 active in matvec

// symbol at t = T-1 = 11 for each batch element
__device__ __align__(16) unsigned char g_sym[BATCH];

// ---------------- JAX threefry2x32 (20 rounds) ----------------
__device__ __forceinline__ uint2 threefry(uint32_t k0, uint32_t k1,
                                          uint32_t x0, uint32_t x1) {
    uint32_t k2 = k0 ^ k1 ^ 0x1BD11BDAu;
    x0 += k0; x1 += k1;
#define TF_RND(r) { x0 += x1; x1 = (x1 << (r)) | (x1 >> (32 - (r))); x1 ^= x0; }
    TF_RND(13) TF_RND(15) TF_RND(26) TF_RND(6)   x0 += k1; x1 += k2 + 1u;
    TF_RND(17) TF_RND(29) TF_RND(16) TF_RND(24)  x0 += k2; x1 += k0 + 2u;
    TF_RND(13) TF_RND(15) TF_RND(26) TF_RND(6)   x0 += k0; x1 += k1 + 3u;
    TF_RND(17) TF_RND(29) TF_RND(16) TF_RND(24)  x0 += k1; x1 += k2 + 4u;
    TF_RND(13) TF_RND(15) TF_RND(26) TF_RND(6)   x0 += k2; x1 += k0 + 5u;
#undef TF_RND
    return make_uint2(x0, x1);
}

// JAX uniform(minval=1e-20, maxval=1.0) -> gumbel
__device__ __forceinline__ float gumbel_from_bits(uint32_t bits) {
    float u = __uint_as_float((bits >> 9) | 0x3F800000u) - 1.0f;
    u = fmaxf(u, 1e-20f);              // == max(minval, u*(max-min)+min) in fp32
    return -logf(-logf(u));
}

// ---------------- phase 1: grammar expansion -> s11[b] ----------------
// jax_threefry_partitionable=True semantics:
//   subkey t  = threefry(key(42)=(0,42), x0=0, x1=t)            -> (ka, kb)
//   bits(i)   = out0 ^ out1 of threefry((ka,kb), x0=0, x1=i)    (32-bit path XORs lanes)
__global__ void grammar_kernel(const float* __restrict__ one_hot,
                               const float* __restrict__ gmat) {
    __shared__ float gm[NSYM * NSYM];
    __shared__ uint32_t ka_s[11], kb_s[11];
    const int tid = threadIdx.x;
    if (tid < NSYM * NSYM) gm[tid] = gmat[tid];
    if (tid < 11) {
        uint2 r = threefry(0u, 42u, 0u, (uint32_t)tid);
        ka_s[tid] = r.x; kb_s[tid] = r.y;
    }
    __syncthreads();

    const int b = blockIdx.x * blockDim.x + tid;   // b in [0, BATCH)
    if (b >= BATCH) return;

    // initial symbol from one-hot row (first-max, matches jnp.argmax)
    int s = 0;
    {
        float bv = -1.0f;
        #pragma unroll
        for (int j = 0; j < NSYM; j++) {
            float v = one_hot[b * NSYM + j];
            if (v > bv) { bv = v; s = j; }
        }
    }

    // 11 expansion steps; symbol 11 is absorbing.
    // RNG is counter-based per element (b*12+j), so skipping absorbed rows is safe.
    #pragma unroll 1
    for (int t = 0; t < 11; t++) {
        if (s == NSYM - 1) break;
        const uint32_t ka = ka_s[t], kb = kb_s[t];
        float best = -1e30f;
        int arg = 0;
        #pragma unroll
        for (int j = 0; j < NSYM; j++) {
            uint2 r = threefry(ka, kb, 0u, (uint32_t)(b * NSYM + j));
            float v = gm[s * NSYM + j] + gumbel_from_bits(r.x ^ r.y);
            if (v > best) { best = v; arg = j; }
        }
        s = arg;
    }
    g_sym[b] = (unsigned char)s;
}

// ---------------- f32x2 packed-FMA helpers (Blackwell) ----------------
__device__ __forceinline__ unsigned long long fma2(unsigned long long a,
                                                   unsigned long long b,
                                                   unsigned long long c) {
    unsigned long long d;
    asm("fma.rn.f32x2 %0, %1, %2, %3;" : "=l"(d) : "l"(a), "l"(b), "l"(c));
    return d;
}
__device__ __forceinline__ unsigned long long pk(float lo, float hi) {
    unsigned long long r;
    asm("mov.b64 %0, {%1, %2};" : "=l"(r) : "f"(lo), "f"(hi));
    return r;
}
__device__ __forceinline__ float2 upk(unsigned long long v) {
    float2 f;
    asm("mov.b64 {%0, %1}, %2;" : "=f"(f.x), "=f"(f.y) : "l"(v));
    return f;
}

__device__ __forceinline__ float sigf(float x) {
    return __fdividef(1.0f, 1.0f + __expf(-x));
}

// ---------------- phase 2: single sequential LSTM chain ----------------
// thread r in [0,400) owns gate row r, W_hh row in 50 f32x2 registers.
// threads [0,100) own hidden dim j = r and carry c[j] in a register.
__global__ void __launch_bounds__(LSTM_THREADS, 1)
lstm_kernel(const float* __restrict__ Wih,
            const float* __restrict__ Whh,
            float* __restrict__ out) {
    __shared__ __align__(16) float h_sm[HID];
    __shared__ float gate_sm[GATES];
    __shared__ float wih_s[GATES * NSYM];
    __shared__ __align__(16) unsigned char sym_s[BATCH];

    const int r = threadIdx.x;

    for (int k = r; k < GATES * NSYM; k += LSTM_THREADS) wih_s[k] = Wih[k];
    {
        const uint4* src = (const uint4*)g_sym;
        uint4* dst = (uint4*)sym_s;
        for (int k = r; k < BATCH / 16; k += LSTM_THREADS) dst[k] = src[k];
    }
    if (r < HID) h_sm[r] = 0.0f;

    unsigned long long w[50];
    if (r < GATES) {
        const unsigned long long* p = (const unsigned long long*)(Whh + r * HID);
        #pragma unroll
        for (int k = 0; k < 50; k++) w[k] = p[k];
    }
    float c = 0.0f;
    __syncthreads();

    #pragma unroll 1
    for (int step = 0; step < BATCH; ++step) {
        const int s = sym_s[step];
        if (r < GATES) {
            unsigned long long a0 = pk(wih_s[r * NSYM + s], 0.0f);
            unsigned long long a1 = pk(0.0f, 0.0f);
            const ulonglong2* h2 = (const ulonglong2*)h_sm;
            #pragma unroll
            for (int k = 0; k < 25; k++) {
                ulonglong2 hv = h2[k];                 // h[4k..4k+3] broadcast
                a0 = fma2(w[2 * k],     hv.x, a0);
                a1 = fma2(w[2 * k + 1], hv.y, a1);
            }
            float2 f0 = upk(a0), f1 = upk(a1);
            gate_sm[r] = (f0.x + f1.x) + (f0.y + f1.y);
        }
        __syncthreads();
        if (r < HID) {
            float gi = gate_sm[r];
            float gf = gate_sm[r + HID];
            float gg = gate_sm[r + 2 * HID];
            float go = gate_sm[r + 3 * HID];
            c = sigf(gf) * c + sigf(gi) * tanhf(gg);
            float h = sigf(go) * tanhf(c);
            h_sm[r] = h;
            out[step * HID + r] = h;
        }
        __syncthreads();
    }
}

extern "C" void kernel_launch(void* const* d_in, const int* in_sizes, int n_in,
                              void* d_out, int out_size) {
    const float* one_hot = (const float*)d_in[0];   // [16384, 12]
    const float* gmat    = (const float*)d_in[1];   // [12, 12]
    const float* Wih     = (const float*)d_in[2];   // [400, 12]
    const float* Whh     = (const float*)d_in[3];   // [400, 100]
    float* out = (float*)d_out;                     // [16384, 100]

    grammar_kernel<<<64, 256>>>(one_hot, gmat);
    lstm_kernel<<<1, LSTM_THREADS>>>(Wih, Whh, out);
}

// round 5
// speedup vs baseline: 1.0105x; 1.0105x over previous
#include <cuda_runtime.h>
#include <cstdint>

#define NSYM   12
#define HID    100
#define BATCH  16384
#define GATES  400            // 4*HID
#define LSTM_THREADS 416      // 13 warps; threads 0..399 active in matvec

// symbol at t = T-1 = 11 for each batch element
__device__ __align__(16) unsigned char g_sym[BATCH];

// ---------------- JAX threefry2x32 (20 rounds) ----------------
__device__ __forceinline__ uint2 threefry(uint32_t k0, uint32_t k1,
                                          uint32_t x0, uint32_t x1) {
    uint32_t k2 = k0 ^ k1 ^ 0x1BD11BDAu;
    x0 += k0; x1 += k1;
#define TF_RND(r) { x0 += x1; x1 = (x1 << (r)) | (x1 >> (32 - (r))); x1 ^= x0; }
    TF_RND(13) TF_RND(15) TF_RND(26) TF_RND(6)   x0 += k1; x1 += k2 + 1u;
    TF_RND(17) TF_RND(29) TF_RND(16) TF_RND(24)  x0 += k2; x1 += k0 + 2u;
    TF_RND(13) TF_RND(15) TF_RND(26) TF_RND(6)   x0 += k0; x1 += k1 + 3u;
    TF_RND(17) TF_RND(29) TF_RND(16) TF_RND(24)  x0 += k1; x1 += k2 + 4u;
    TF_RND(13) TF_RND(15) TF_RND(26) TF_RND(6)   x0 += k2; x1 += k0 + 5u;
#undef TF_RND
    return make_uint2(x0, x1);
}

// JAX uniform(minval=1e-20, maxval=1.0) -> gumbel
__device__ __forceinline__ float gumbel_from_bits(uint32_t bits) {
    float u = __uint_as_float((bits >> 9) | 0x3F800000u) - 1.0f;
    u = fmaxf(u, 1e-20f);              // == max(minval, u*(max-min)+min) in fp32
    return -logf(-logf(u));
}

// ---------------- phase 1: grammar expansion -> s11[b] ----------------
// jax_threefry_partitionable=True semantics:
//   subkey t  = threefry(key(42)=(0,42), x0=0, x1=t)            -> (ka, kb)
//   bits(i)   = out0 ^ out1 of threefry((ka,kb), x0=0, x1=i)    (32-bit path XORs lanes)
__global__ void grammar_kernel(const float* __restrict__ one_hot,
                               const float* __restrict__ gmat) {
    __shared__ float gm[NSYM * NSYM];
    __shared__ uint32_t ka_s[11], kb_s[11];
    const int tid = threadIdx.x;
    if (tid < NSYM * NSYM) gm[tid] = gmat[tid];
    if (tid < 11) {
        uint2 r = threefry(0u, 42u, 0u, (uint32_t)tid);
        ka_s[tid] = r.x; kb_s[tid] = r.y;
    }
    __syncthreads();

    const int b = blockIdx.x * blockDim.x + tid;   // b in [0, BATCH)
    if (b >= BATCH) return;

    // initial symbol from one-hot row (first-max, matches jnp.argmax)
    int s = 0;
    {
        float bv = -1.0f;
        #pragma unroll
        for (int j = 0; j < NSYM; j++) {
            float v = one_hot[b * NSYM + j];
            if (v > bv) { bv = v; s = j; }
        }
    }

    // 11 expansion steps; symbol 11 is absorbing.
    // RNG is counter-based per element (b*12+j), so skipping absorbed rows is safe.
    #pragma unroll 1
    for (int t = 0; t < 11; t++) {
        if (s == NSYM - 1) break;
        const uint32_t ka = ka_s[t], kb = kb_s[t];
        float best = -1e30f;
        int arg = 0;
        #pragma unroll
        for (int j = 0; j < NSYM; j++) {
            uint2 r = threefry(ka, kb, 0u, (uint32_t)(b * NSYM + j));
            float v = gm[s * NSYM + j] + gumbel_from_bits(r.x ^ r.y);
            if (v > best) { best = v; arg = j; }
        }
        s = arg;
    }
    g_sym[b] = (unsigned char)s;
}

// ---------------- f32x2 packed-FMA helpers (Blackwell) ----------------
__device__ __forceinline__ unsigned long long fma2(unsigned long long a,
                                                   unsigned long long b,
                                                   unsigned long long c) {
    unsigned long long d;
    asm("fma.rn.f32x2 %0, %1, %2, %3;" : "=l"(d) : "l"(a), "l"(b), "l"(c));
    return d;
}
__device__ __forceinline__ unsigned long long pk(float lo, float hi) {
    unsigned long long r;
    asm("mov.b64 %0, {%1, %2};" : "=l"(r) : "f"(lo), "f"(hi));
    return r;
}
__device__ __forceinline__ float2 upk(unsigned long long v) {
    float2 f;
    asm("mov.b64 {%0, %1}, %2;" : "=f"(f.x), "=f"(f.y) : "l"(v));
    return f;
}

__device__ __forceinline__ float sigf(float x) {
    return __fdividef(1.0f, 1.0f + __expf(-x));
}

// ---------------- phase 2: single sequential LSTM chain ----------------
// thread r in [0,400) owns gate row r, W_hh row in 50 f32x2 registers.
// threads [0,100) own hidden dim j = r and carry c[j] in a register.
__global__ void __launch_bounds__(LSTM_THREADS, 1)
lstm_kernel(const float* __restrict__ Wih,
            const float* __restrict__ Whh,
            float* __restrict__ out) {
    __shared__ __align__(16) float h_sm[HID];
    __shared__ float gate_sm[GATES];
    __shared__ float wih_s[GATES * NSYM];
    __shared__ __align__(16) unsigned char sym_s[BATCH];

    const int r = threadIdx.x;

    for (int k = r; k < GATES * NSYM; k += LSTM_THREADS) wih_s[k] = Wih[k];
    {
        const uint4* src = (const uint4*)g_sym;
        uint4* dst = (uint4*)sym_s;
        for (int k = r; k < BATCH / 16; k += LSTM_THREADS) dst[k] = src[k];
    }
    if (r < HID) h_sm[r] = 0.0f;

    unsigned long long w[50];
    if (r < GATES) {
        const unsigned long long* p = (const unsigned long long*)(Whh + r * HID);
        #pragma unroll
        for (int k = 0; k < 50; k++) w[k] = p[k];
    }
    float c = 0.0f;
    __syncthreads();

    #pragma unroll 1
    for (int step = 0; step < BATCH; ++step) {
        const int s = sym_s[step];
        if (r < GATES) {
            unsigned long long a0 = pk(wih_s[r * NSYM + s], 0.0f);
            unsigned long long a1 = pk(0.0f, 0.0f);
            const ulonglong2* h2 = (const ulonglong2*)h_sm;
            #pragma unroll
            for (int k = 0; k < 25; k++) {
                ulonglong2 hv = h2[k];                 // h[4k..4k+3] broadcast
                a0 = fma2(w[2 * k],     hv.x, a0);
                a1 = fma2(w[2 * k + 1], hv.y, a1);
            }
            float2 f0 = upk(a0), f1 = upk(a1);
            gate_sm[r] = (f0.x + f1.x) + (f0.y + f1.y);
        }
        __syncthreads();
        if (r < HID) {
            float gi = gate_sm[r];
            float gf = gate_sm[r + HID];
            float gg = gate_sm[r + 2 * HID];
            float go = gate_sm[r + 3 * HID];
            c = sigf(gf) * c + sigf(gi) * tanhf(gg);
            float h = sigf(go) * tanhf(c);
            h_sm[r] = h;
            out[step * HID + r] = h;
        }
        __syncthreads();
    }
}

extern "C" void kernel_launch(void* const* d_in, const int* in_sizes, int n_in,
                              void* d_out, int out_size) {
    const float* one_hot = (const float*)d_in[0];   // [16384, 12]
    const float* gmat    = (const float*)d_in[1];   // [12, 12]
    const float* Wih     = (const float*)d_in[2];   // [400, 12]
    const float* Whh     = (const float*)d_in[3];   // [400, 100]
    float* out = (float*)d_out;                     // [16384, 100]

    grammar_kernel<<<64, 256>>>(one_hot, gmat);
    lstm_kernel<<<1, LSTM_THREADS>>>(Wih, Whh, out);
}